// round 1
// baseline (speedup 1.0000x reference)
#include <cuda_runtime.h>

// ---------------- scratch buffers (device globals: no allocation allowed) ----
__device__ float g_l0[8 * 256 * 64 * 64];   // merged lateral L0
__device__ float g_l1[8 * 256 * 32 * 32];   // merged lateral L1
__device__ float g_l2[8 * 256 * 16 * 16];   // lateral L2
__device__ float g_f [8 * 256 * 64 * 64];   // FPN feature (per-level reuse)
__device__ float g_t1[8 * 256 * 64 * 64];   // tower temp 1
__device__ float g_t2[8 * 256 * 64 * 64];   // tower temp 2

// ---------------- generic direct conv ---------------------------------------
// Tile: 32 output channels x 128 pixels (16 wide x 8 high). 256 threads.
// Each thread: 4 couts x 4 pixels = 16 accumulators.
// Requires W % 16 == 0 and H % 8 == 0 (holds for 64/32/16).
template <int KS, bool RELU>
__global__ __launch_bounds__(256) void conv_kernel(
    const float* __restrict__ in, const float* __restrict__ wgt,
    const float* __restrict__ bias, float* __restrict__ out,
    int Cin, int Cout, int H, int W,
    long long ob, long long oc, long long op)
{
    constexpr int CK  = 8;
    constexpr int PH  = 8 + KS - 1;
    constexpr int PW  = 16 + KS - 1;
    constexpr int PAD = KS / 2;

    __shared__ __align__(16) float ism[CK][PH][PW];
    __shared__ __align__(16) float wsm[CK * KS * KS][32];

    const int tid  = threadIdx.x;
    const int co_g = tid & 7;        // 8 cout groups of 4
    const int q    = tid >> 3;       // 32 pixel quads
    const int row  = q >> 2;         // 0..7
    const int xb   = (q & 3) * 4;    // 0,4,8,12

    const int txs    = W >> 4;
    const int tile_x = (blockIdx.x % txs) << 4;
    const int tile_y = (blockIdx.x / txs) << 3;
    const int co0    = blockIdx.y << 5;
    const int bz     = blockIdx.z;

    float acc[4][4];
#pragma unroll
    for (int j = 0; j < 4; ++j)
#pragma unroll
        for (int p = 0; p < 4; ++p) acc[j][p] = 0.f;

    for (int cin0 = 0; cin0 < Cin; cin0 += CK) {
        // --- stage input patch (with zero padding at borders) ---
        constexpr int PSZ = CK * PH * PW;
        for (int e = tid; e < PSZ; e += 256) {
            int ci = e / (PH * PW);
            int r  = (e / PW) % PH;
            int c  = e % PW;
            int gy = tile_y + r - PAD;
            int gx = tile_x + c - PAD;
            float v = 0.f;
            if (gy >= 0 && gy < H && gx >= 0 && gx < W)
                v = in[(((long long)bz * Cin + cin0 + ci) * H + gy) * W + gx];
            ism[ci][r][c] = v;
        }
        // --- stage weights as [ci*KS*KS + k][co] ---
        constexpr int WSZ = CK * KS * KS * 32;
        for (int e = tid; e < WSZ; e += 256) {
            int co   = e & 31;
            int kidx = e >> 5;
            int ci   = kidx / (KS * KS);
            int k    = kidx % (KS * KS);
            int gco  = co0 + co;
            float v = 0.f;
            if (gco < Cout)
                v = wgt[((long long)gco * Cin + cin0 + ci) * (KS * KS) + k];
            wsm[kidx][co] = v;
        }
        __syncthreads();

#pragma unroll 2
        for (int ci = 0; ci < CK; ++ci) {
#pragma unroll
            for (int ky = 0; ky < KS; ++ky) {
#pragma unroll
                for (int kx = 0; kx < KS; ++kx) {
                    const float4 wv =
                        *(const float4*)&wsm[(ci * KS + ky) * KS + kx][co_g * 4];
                    const float* ir = &ism[ci][row + ky][xb + kx];
                    const float i0 = ir[0], i1 = ir[1], i2 = ir[2], i3 = ir[3];
                    acc[0][0] = fmaf(wv.x, i0, acc[0][0]);
                    acc[0][1] = fmaf(wv.x, i1, acc[0][1]);
                    acc[0][2] = fmaf(wv.x, i2, acc[0][2]);
                    acc[0][3] = fmaf(wv.x, i3, acc[0][3]);
                    acc[1][0] = fmaf(wv.y, i0, acc[1][0]);
                    acc[1][1] = fmaf(wv.y, i1, acc[1][1]);
                    acc[1][2] = fmaf(wv.y, i2, acc[1][2]);
                    acc[1][3] = fmaf(wv.y, i3, acc[1][3]);
                    acc[2][0] = fmaf(wv.z, i0, acc[2][0]);
                    acc[2][1] = fmaf(wv.z, i1, acc[2][1]);
                    acc[2][2] = fmaf(wv.z, i2, acc[2][2]);
                    acc[2][3] = fmaf(wv.z, i3, acc[2][3]);
                    acc[3][0] = fmaf(wv.w, i0, acc[3][0]);
                    acc[3][1] = fmaf(wv.w, i1, acc[3][1]);
                    acc[3][2] = fmaf(wv.w, i2, acc[3][2]);
                    acc[3][3] = fmaf(wv.w, i3, acc[3][3]);
                }
            }
        }
        __syncthreads();
    }

    const int y     = tile_y + row;
    const int xbase = tile_x + xb;
#pragma unroll
    for (int j = 0; j < 4; ++j) {
        const int co = co0 + co_g * 4 + j;
        if (co >= Cout) break;
        const float bv = bias[co];
#pragma unroll
        for (int p = 0; p < 4; ++p) {
            float v = acc[j][p] + bv;
            if (RELU) v = fmaxf(v, 0.f);
            out[(long long)bz * ob + (long long)co * oc +
                (long long)(y * W + xbase + p) * op] = v;
        }
    }
}

// ---------------- nearest 2x upsample + add ----------------------------------
__global__ void up2add_kernel(float* __restrict__ big, const float* __restrict__ small,
                              int Hs, int Ws)
{
    const int H = Hs * 2, W = Ws * 2;
    const long long total = 8LL * 256 * H * W;
    long long idx = (long long)blockIdx.x * blockDim.x + threadIdx.x;
    if (idx >= total) return;
    int x  = (int)(idx % W);
    int y  = (int)((idx / W) % H);
    long long bc = idx / ((long long)W * H);
    big[idx] += small[(bc * Hs + (y >> 1)) * Ws + (x >> 1)];
}

// ---------------- anchors -----------------------------------------------------
__global__ void anchors_kernel(float* __restrict__ out)
{
    int i = blockIdx.x * blockDim.x + threadIdx.x;
    if (i >= 16128) return;
    int lvl, rem;
    if (i < 12288)      { lvl = 0; rem = i; }
    else if (i < 15360) { lvl = 1; rem = i - 12288; }
    else                { lvl = 2; rem = i - 15360; }
    const int w        = 64 >> lvl;
    const float stride = 8.0f * (float)(1 << lvl);
    const float bs     = 32.0f * (float)(1 << lvl);
    const int a = rem % 3;
    const int s = rem / 3;
    const int x = s % w;
    const int y = s / w;
    const float sq[3] = {0.70710678118654752f, 1.0f, 1.41421356237309505f};
    const float hw = bs * sq[a] * 0.5f;
    const float hh = bs / sq[a] * 0.5f;
    const float cx = (float)x * stride;
    const float cy = (float)y * stride;
    float* o = out + (long long)i * 4;
    o[0] = cx - hw; o[1] = cy - hh; o[2] = cx + hw; o[3] = cy + hh;
}

// ---------------- host dispatch ----------------------------------------------
template <int KS>
static void launch_conv(const float* in, const float* w, const float* b, float* out,
                        int Cin, int Cout, int H, int W, bool relu,
                        long long ob, long long oc, long long op)
{
    dim3 grid((W / 16) * (H / 8), (Cout + 31) / 32, 8);
    if (relu)
        conv_kernel<KS, true><<<grid, 256>>>(in, w, b, out, Cin, Cout, H, W, ob, oc, op);
    else
        conv_kernel<KS, false><<<grid, 256>>>(in, w, b, out, Cin, Cout, H, W, ob, oc, op);
}

extern "C" void kernel_launch(void* const* d_in, const int* in_sizes, int n_in,
                              void* d_out, int out_size)
{
    const float* feat3 = (const float*)d_in[0];
    const float* feat4 = (const float*)d_in[1];
    const float* feat5 = (const float*)d_in[2];
    const float* lw0 = (const float*)d_in[3];  const float* lb0 = (const float*)d_in[4];
    const float* lw1 = (const float*)d_in[5];  const float* lb1 = (const float*)d_in[6];
    const float* lw2 = (const float*)d_in[7];  const float* lb2 = (const float*)d_in[8];
    const float* fw0 = (const float*)d_in[9];  const float* fb0 = (const float*)d_in[10];
    const float* fw1 = (const float*)d_in[11]; const float* fb1 = (const float*)d_in[12];
    const float* fw2 = (const float*)d_in[13]; const float* fb2 = (const float*)d_in[14];
    const float* cw0 = (const float*)d_in[15]; const float* cb0 = (const float*)d_in[16];
    const float* cw1 = (const float*)d_in[17]; const float* cb1 = (const float*)d_in[18];
    const float* cw2 = (const float*)d_in[19]; const float* cb2 = (const float*)d_in[20];
    const float* rw0 = (const float*)d_in[21]; const float* rb0 = (const float*)d_in[22];
    const float* rw1 = (const float*)d_in[23]; const float* rb1 = (const float*)d_in[24];
    const float* rw2 = (const float*)d_in[25]; const float* rb2 = (const float*)d_in[26];
    float* out = (float*)d_out;

    float *l0, *l1, *l2, *f, *t1, *t2;
    cudaGetSymbolAddress((void**)&l0, g_l0);
    cudaGetSymbolAddress((void**)&l1, g_l1);
    cudaGetSymbolAddress((void**)&l2, g_l2);
    cudaGetSymbolAddress((void**)&f,  g_f);
    cudaGetSymbolAddress((void**)&t1, g_t1);
    cudaGetSymbolAddress((void**)&t2, g_t2);

    // FPN laterals (1x1 convs)
    launch_conv<1>(feat3, lw0, lb0, l0, 512,  256, 64, 64, false, 256LL * 4096, 4096, 1);
    launch_conv<1>(feat4, lw1, lb1, l1, 1024, 256, 32, 32, false, 256LL * 1024, 1024, 1);
    launch_conv<1>(feat5, lw2, lb2, l2, 2048, 256, 16, 16, false, 256LL * 256,  256,  1);

    // top-down merge: l1 += up2(l2); l0 += up2(l1)
    {
        long long n1 = 8LL * 256 * 32 * 32;
        up2add_kernel<<<(unsigned)((n1 + 255) / 256), 256>>>(l1, l2, 16, 16);
        long long n0 = 8LL * 256 * 64 * 64;
        up2add_kernel<<<(unsigned)((n0 + 255) / 256), 256>>>(l0, l1, 32, 32);
    }

    struct Lvl { const float* lat; const float* fw; const float* fb; int H, W; long long poff; };
    const Lvl L[3] = {
        { l0, fw0, fb0, 64, 64, 0    },
        { l1, fw1, fb1, 32, 32, 4096 },
        { l2, fw2, fb2, 16, 16, 5120 },
    };

    for (int i = 0; i < 3; ++i) {
        const int H = L[i].H, W = L[i].W;
        const long long hw = (long long)H * W;
        // FPN output conv
        launch_conv<3>(L[i].lat, L[i].fw, L[i].fb, f, 256, 256, H, W, false, 256 * hw, hw, 1);
        // cls tower
        launch_conv<3>(f,  cw0, cb0, t1, 256, 256, H, W, true,  256 * hw, hw, 1);
        launch_conv<3>(t1, cw1, cb1, t2, 256, 256, H, W, true,  256 * hw, hw, 1);
        launch_conv<3>(t2, cw2, cb2, out + L[i].poff * 252,       256, 240, H, W, false,
                       5376LL * 252, 1, 252);
        // reg tower
        launch_conv<3>(f,  rw0, rb0, t1, 256, 256, H, W, true,  256 * hw, hw, 1);
        launch_conv<3>(t1, rw1, rb1, t2, 256, 256, H, W, true,  256 * hw, hw, 1);
        launch_conv<3>(t2, rw2, rb2, out + L[i].poff * 252 + 240, 256, 12,  H, W, false,
                       5376LL * 252, 1, 252);
    }

    // anchors appended after the [8, 5376, 252] tensor
    anchors_kernel<<<(16128 + 255) / 256, 256>>>(out + 10838016LL);
}

// round 3
// speedup vs baseline: 3.2955x; 3.2955x over previous
#include <cuda_runtime.h>
#include <cuda_bf16.h>
#include <cstdint>

#if defined(__CUDA_ARCH_FEAT_SM103_ALL) || defined(__CUDA_ARCH_FEAT_SM100_ALL)
#define HAS_TCGEN05 1
#else
#define HAS_TCGEN05 0
#endif

// ---------------- activation scratch (fp32, NCHW) ----------------------------
__device__ float g_l0[8 * 256 * 64 * 64];
__device__ float g_l1[8 * 256 * 32 * 32];
__device__ float g_l2[8 * 256 * 16 * 16];
__device__ float g_f [8 * 256 * 64 * 64];
__device__ float g_t1[8 * 256 * 64 * 64];
__device__ float g_t2[8 * 256 * 64 * 64];

// ---------------- bf16 hi/lo weight arena (t-major K layout) -----------------
#define WOFF_L0  0LL
#define WOFF_L1  131072LL
#define WOFF_L2  393216LL
#define WOFF_FW0 917504LL
#define WOFF_FW1 1507328LL
#define WOFF_FW2 2097152LL
#define WOFF_CW0 2686976LL
#define WOFF_CW1 3276800LL
#define WOFF_CW2 3866624LL
#define WOFF_RW0 4456448LL
#define WOFF_RW1 5046272LL
#define WOFF_RW2 5636096LL
#define WARENA   5672960LL
__device__ __nv_bfloat16 g_whi[WARENA];
__device__ __nv_bfloat16 g_wlo[WARENA];

// ---------------- helpers ----------------------------------------------------
#define SWZ(off)  ((off) ^ (((off) >> 3) & 0x70))   // 128B-row swizzle
#define SWZA(off) ((off) ^ (((off) >> 4) & 0x70))   // 256B-row swizzle

static __device__ __forceinline__ uint32_t smem_u32(const void* p) {
    uint32_t a;
    asm("{ .reg .u64 t; cvta.to.shared.u64 t, %1; cvt.u32.u64 %0, t; }"
        : "=r"(a) : "l"(p));
    return a;
}

#define LDSM_X4(r0, r1, r2, r3, ad) \
    asm volatile("ldmatrix.sync.aligned.m8n8.x4.shared.b16 {%0,%1,%2,%3}, [%4];" \
                 : "=r"(r0), "=r"(r1), "=r"(r2), "=r"(r3) : "r"(ad))
#define LDSM_X4T(r0, r1, r2, r3, ad) \
    asm volatile("ldmatrix.sync.aligned.m8n8.x4.trans.shared.b16 {%0,%1,%2,%3}, [%4];" \
                 : "=r"(r0), "=r"(r1), "=r"(r2), "=r"(r3) : "r"(ad))
#define LDSM_X2(r0, r1, ad) \
    asm volatile("ldmatrix.sync.aligned.m8n8.x2.shared.b16 {%0,%1}, [%2];" \
                 : "=r"(r0), "=r"(r1) : "r"(ad))
#define MMA16816(d, a, b) \
    asm volatile("mma.sync.aligned.m16n8k16.row.col.f32.bf16.bf16.f32 " \
                 "{%0,%1,%2,%3},{%4,%5,%6,%7},{%8,%9},{%0,%1,%2,%3};" \
                 : "+f"((d)[0]), "+f"((d)[1]), "+f"((d)[2]), "+f"((d)[3]) \
                 : "r"((a)[0]), "r"((a)[1]), "r"((a)[2]), "r"((a)[3]), \
                   "r"((b)[0]), "r"((b)[1]))
#define CVT2BF(dst, hi, lo) \
    asm("cvt.rn.bf16x2.f32 %0, %1, %2;" : "=r"(dst) : "f"(hi), "f"(lo))

#if HAS_TCGEN05
static __device__ __forceinline__ uint32_t elect_one() {
    uint32_t p;
    asm volatile("{ .reg .pred p; elect.sync _|p, 0xFFFFFFFF; selp.b32 %0, 1, 0, p; }"
                 : "=r"(p));
    return p;
}
static __device__ __forceinline__ void mbar_wait(uint32_t mb, uint32_t ph) {
    asm volatile(
        "{\n\t.reg .pred P;\n"
        "LAB%=:\n\t"
        "mbarrier.try_wait.parity.acquire.cta.shared::cta.b64 P, [%0], %1, 0x989680;\n\t"
        "@!P bra LAB%=;\n\t}"
        :: "r"(mb), "r"(ph) : "memory");
}
static constexpr uint64_t DESC_BASE_SW128 =
    (uint64_t(2) << 61) | (uint64_t(1) << 46) | (uint64_t(64) << 32) | (uint64_t(1) << 16);
static __device__ __forceinline__ uint64_t mk_desc(uint32_t addr) {
    return DESC_BASE_SW128 | ((uint64_t)(addr >> 4) & 0x3FFF);
}
static __device__ __forceinline__ void mma_f16_ss(uint32_t d, uint64_t a, uint64_t b,
                                                  uint32_t idesc, uint32_t acc) {
    asm volatile(
        "{\n\t.reg .pred p;\n\t"
        "setp.ne.u32 p, %5, 0;\n\t"
        "tcgen05.mma.cta_group::1.kind::f16 [%0], %1, %2, %3, {%4,%4,%4,%4}, p;\n\t}"
        :: "r"(d), "l"(a), "l"(b), "r"(idesc), "r"(0u), "r"(acc) : "memory");
}
#define LD32X32_X32(r, ta) \
    asm volatile( \
        "tcgen05.ld.sync.aligned.32x32b.x32.b32 " \
        "{%0, %1, %2, %3, %4, %5, %6, %7, " \
        " %8, %9, %10, %11, %12, %13, %14, %15, " \
        " %16, %17, %18, %19, %20, %21, %22, %23, " \
        " %24, %25, %26, %27, %28, %29, %30, %31}, [%32];" \
        : "=r"((r)[0]),  "=r"((r)[1]),  "=r"((r)[2]),  "=r"((r)[3]), \
          "=r"((r)[4]),  "=r"((r)[5]),  "=r"((r)[6]),  "=r"((r)[7]), \
          "=r"((r)[8]),  "=r"((r)[9]),  "=r"((r)[10]), "=r"((r)[11]), \
          "=r"((r)[12]), "=r"((r)[13]), "=r"((r)[14]), "=r"((r)[15]), \
          "=r"((r)[16]), "=r"((r)[17]), "=r"((r)[18]), "=r"((r)[19]), \
          "=r"((r)[20]), "=r"((r)[21]), "=r"((r)[22]), "=r"((r)[23]), \
          "=r"((r)[24]), "=r"((r)[25]), "=r"((r)[26]), "=r"((r)[27]), \
          "=r"((r)[28]), "=r"((r)[29]), "=r"((r)[30]), "=r"((r)[31]) \
        : "r"(ta))
#define LD32X32_X16(r, ta) \
    asm volatile( \
        "tcgen05.ld.sync.aligned.32x32b.x16.b32 " \
        "{%0, %1, %2, %3, %4, %5, %6, %7, " \
        " %8, %9, %10, %11, %12, %13, %14, %15}, [%16];" \
        : "=r"((r)[0]),  "=r"((r)[1]),  "=r"((r)[2]),  "=r"((r)[3]), \
          "=r"((r)[4]),  "=r"((r)[5]),  "=r"((r)[6]),  "=r"((r)[7]), \
          "=r"((r)[8]),  "=r"((r)[9]),  "=r"((r)[10]), "=r"((r)[11]), \
          "=r"((r)[12]), "=r"((r)[13]), "=r"((r)[14]), "=r"((r)[15]) \
        : "r"(ta))
#define TC_WAIT_LD() asm volatile("tcgen05.wait::ld.sync.aligned;" ::: "memory")
#endif  // HAS_TCGEN05

// ---------------- weight pre-transform: fp32 [co][ci][taps] -> bf16 hi/lo ----
__global__ void wt_kernel(const float* __restrict__ src, __nv_bfloat16* __restrict__ hi,
                          __nv_bfloat16* __restrict__ lo, int coutA, long long n,
                          int Cin, int taps)
{
    long long idx = (long long)blockIdx.x * 256 + threadIdx.x;
    if (idx >= n) return;
    const int K = Cin * taps;
    long long co = idx / K;
    int r  = (int)(idx - co * K);
    int t  = r / Cin;
    int ci = r - t * Cin;
    float v = 0.f;
    if (co < coutA) v = src[co * K + (long long)ci * taps + t];
    __nv_bfloat16 h = __float2bfloat16(v);
    float rr = v - __bfloat162float(h);
    hi[idx] = h;
    lo[idx] = __float2bfloat16(rr);
}

// ---------------- implicit-GEMM conv (tcgen05 if available, else mma.sync) ---
// D[M=128 pixels][N=NTILE couts] = sum_K A[px][k]*W[co][k], bf16 hi/lo 3-term.
template <int NTILE, bool RELU>
__global__ void __launch_bounds__(256, 2)
gemm_conv(const float* __restrict__ in,
          const __nv_bfloat16* __restrict__ whi,
          const __nv_bfloat16* __restrict__ wlo,
          const float* __restrict__ bias,
          float* __restrict__ out,
          int Cin, int CoutActual, int K, int taps, int H, int Wd,
          long long ob, long long oc, long long op)
{
    extern __shared__ char dsm[];
    const int tid = threadIdx.x;

    uint32_t u0  = smem_u32(dsm);
    uint32_t pad = (1024u - (u0 & 1023u)) & 1023u;
    char*    db  = dsm + pad;
    uint32_t dyn = u0 + pad;

    const int HW  = H * Wd;
    const int co0 = blockIdx.y * NTILE;
    const int bz  = blockIdx.z;
    const int p0  = blockIdx.x * 128;
    const int nchunks = K >> 6;

#if HAS_TCGEN05
    // ======================= tcgen05 path ====================================
    __shared__ uint32_t s_tmem;
    __shared__ __align__(8) unsigned long long s_mbar;
    const int wid = tid >> 5;
    const uint32_t mb = smem_u32(&s_mbar);

    constexpr uint32_t IDESC =
        (1u << 4) | (1u << 7) | (1u << 10) | ((uint32_t)(NTILE / 8) << 17) | (8u << 24);

    if (wid == 0) {
        asm volatile("tcgen05.alloc.cta_group::1.sync.aligned.shared::cta.b32 [%0], %1;"
                     :: "r"(smem_u32(&s_tmem)), "r"(128u) : "memory");
        asm volatile("tcgen05.relinquish_alloc_permit.cta_group::1.sync.aligned;");
    }
    if (tid == 0)
        asm volatile("mbarrier.init.shared.b64 [%0], 1;" :: "r"(mb) : "memory");
    __syncthreads();
    const uint32_t tmem = s_tmem;

    const uint64_t dAhi = mk_desc(dyn);
    const uint64_t dAlo = mk_desc(dyn + 16384);
    const uint64_t dBhi = mk_desc(dyn + 32768);
    const uint64_t dBlo = mk_desc(dyn + 49152);

    const int arow = tid >> 1;
    const int kb   = (tid & 1) * 32;
    const int pA   = p0 + arow;
    const int pyA  = pA / Wd, pxA = pA % Wd;

    for (int chunk = 0; chunk < nchunks; ++chunk) {
        const int k0 = chunk << 6;
        {
            int t   = k0 / Cin;
            int ci0 = k0 - t * Cin;
            int dy = 0, dx = 0;
            if (taps == 9) { dy = t / 3 - 1; dx = t - (t / 3) * 3 - 1; }
            int yy = pyA + dy, xx = pxA + dx;
            bool ok = (yy >= 0) && (yy < H) && (xx >= 0) && (xx < Wd);
            const float* src = in + (((long long)bz * Cin + ci0 + kb) * H + yy) * Wd + xx;
            const uint32_t rowoff = (uint32_t)arow * 128u;
#pragma unroll 8
            for (int i = 0; i < 32; ++i) {
                float v = ok ? __ldg(src + (long long)i * HW) : 0.f;
                __nv_bfloat16 h = __float2bfloat16(v);
                float rr = v - __bfloat162float(h);
                __nv_bfloat16 l = __float2bfloat16(rr);
                uint32_t off = SWZ(rowoff + (uint32_t)(kb + i) * 2u);
                *(__nv_bfloat16*)(db + off)         = h;
                *(__nv_bfloat16*)(db + 16384 + off) = l;
            }
        }
        {
            const char* sH = (const char*)(whi + (long long)co0 * K + k0);
            const char* sL = (const char*)(wlo + (long long)co0 * K + k0);
            const long long rowb = (long long)K * 2;
#pragma unroll
            for (int j = 0; j < (NTILE * 8 + 255) / 256; ++j) {
                int idx = tid + j * 256;
                if (idx < NTILE * 8) {
                    int r = idx >> 3, c = idx & 7;
                    uint4 hv = *(const uint4*)(sH + r * rowb + c * 16);
                    uint4 lv = *(const uint4*)(sL + r * rowb + c * 16);
                    uint32_t off = SWZ((uint32_t)r * 128u + (uint32_t)c * 16u);
                    *(uint4*)(db + 32768 + off) = hv;
                    *(uint4*)(db + 49152 + off) = lv;
                }
            }
        }
        asm volatile("fence.proxy.async.shared::cta;" ::: "memory");
        __syncthreads();

        if (wid == 0) {
            if (elect_one()) {
#pragma unroll
                for (int s = 0; s < 4; ++s) {
                    uint64_t o = (uint64_t)s * 2;
                    uint32_t a0 = (chunk == 0 && s == 0) ? 0u : 1u;
                    mma_f16_ss(tmem, dAhi + o, dBhi + o, IDESC, a0);
                    mma_f16_ss(tmem, dAlo + o, dBhi + o, IDESC, 1u);
                    mma_f16_ss(tmem, dAhi + o, dBlo + o, IDESC, 1u);
                }
                asm volatile(
                    "tcgen05.commit.cta_group::1.mbarrier::arrive::one.shared::cluster.b64 [%0];"
                    :: "r"(mb) : "memory");
            }
        }
        mbar_wait(mb, (uint32_t)(chunk & 1));
    }
    asm volatile("tcgen05.fence::after_thread_sync;" ::: "memory");

    if (tid < 128) {
        const long long obase = (long long)bz * ob + (long long)(p0 + tid) * op;
        if constexpr (NTILE == 128) {
            for (int blk = 0; blk < 4; ++blk) {
                uint32_t r[32];
                LD32X32_X32(r, tmem + blk * 32);
                TC_WAIT_LD();
#pragma unroll
                for (int j = 0; j < 32; ++j) {
                    int co = co0 + blk * 32 + j;
                    if (co < CoutActual) {
                        float v = __uint_as_float(r[j]) + bias[co];
                        if (RELU) v = fmaxf(v, 0.f);
                        out[obase + (long long)co * oc] = v;
                    }
                }
            }
        } else {
            uint32_t r[16];
            LD32X32_X16(r, tmem);
            TC_WAIT_LD();
#pragma unroll
            for (int j = 0; j < 16; ++j) {
                int co = co0 + j;
                if (co < CoutActual) {
                    float v = __uint_as_float(r[j]) + bias[co];
                    if (RELU) v = fmaxf(v, 0.f);
                    out[obase + (long long)co * oc] = v;
                }
            }
        }
    }
    __syncthreads();
    if (tid == 0)
        asm volatile("mbarrier.inval.shared.b64 [%0];" :: "r"(mb) : "memory");
    __syncthreads();
    if (wid == 0)
        asm volatile("tcgen05.dealloc.cta_group::1.sync.aligned.b32 %0, %1;"
                     :: "r"(tmem), "r"(128u));
#else
    // ======================= mma.sync (HMMA) fallback ========================
    constexpr int WN  = NTILE / 2;   // per-warp N extent
    constexpr int N8T = WN / 8;      // n8 tiles per warp
    const int wid  = tid >> 5, lane = tid & 31;
    const int m_base = (wid & 3) * 32;
    const int n_base = (wid >> 2) * WN;

    const uint32_t aHI = dyn, aLO = dyn + 16384;
    const uint32_t bHI = dyn + 32768, bLO = dyn + 49152;

    float acc[2][N8T][4];
#pragma unroll
    for (int mt = 0; mt < 2; ++mt)
#pragma unroll
        for (int nt = 0; nt < N8T; ++nt)
#pragma unroll
            for (int r = 0; r < 4; ++r) acc[mt][nt][r] = 0.f;

    const int g = lane >> 3, lr = lane & 7;

    for (int chunk = 0; chunk < nchunks; ++chunk) {
        const int k0 = chunk << 6;
        int t   = k0 / Cin;
        int ci0 = k0 - t * Cin;
        int dy = 0, dx = 0;
        if (taps == 9) { dy = t / 3 - 1; dx = t - (t / 3) * 3 - 1; }

        // ---- A staging: [k=64][px=128] bf16, 256B rows, SWZA ----
#pragma unroll
        for (int j = 0; j < 8; ++j) {
            int idx = tid + j * 256;
            int k = idx >> 5, q = idx & 31;
            int pq = p0 + q * 4;
            float v[4];
            const long long base = ((long long)bz * Cin + ci0 + k) * H;
            if (dx == 0) {
                int py = pq / Wd;
                int xx0 = pq - py * Wd;
                int yy = py + dy;
                if (yy >= 0 && yy < H) {
                    const float4 f4 = *(const float4*)(in + (base + yy) * Wd + xx0);
                    v[0] = f4.x; v[1] = f4.y; v[2] = f4.z; v[3] = f4.w;
                } else v[0] = v[1] = v[2] = v[3] = 0.f;
            } else {
#pragma unroll
                for (int e = 0; e < 4; ++e) {
                    int p = pq + e;
                    int py = p / Wd, px = p - py * Wd;
                    int yy = py + dy, xx = px + dx;
                    v[e] = (yy >= 0 && yy < H && xx >= 0 && xx < Wd)
                               ? __ldg(in + (base + yy) * Wd + xx) : 0.f;
                }
            }
            uint32_t h01, h23, l01, l23;
            CVT2BF(h01, v[1], v[0]);
            CVT2BF(h23, v[3], v[2]);
            float r0 = v[0] - __uint_as_float((h01 & 0xFFFFu) << 16);
            float r1 = v[1] - __uint_as_float(h01 & 0xFFFF0000u);
            float r2 = v[2] - __uint_as_float((h23 & 0xFFFFu) << 16);
            float r3 = v[3] - __uint_as_float(h23 & 0xFFFF0000u);
            CVT2BF(l01, r1, r0);
            CVT2BF(l23, r3, r2);
            uint32_t off = SWZA((uint32_t)k * 256u + (uint32_t)q * 8u);
            *(uint2*)(db + off)         = make_uint2(h01, h23);
            *(uint2*)(db + 16384 + off) = make_uint2(l01, l23);
        }
        // ---- B staging: [co=NTILE][k=64] bf16, 128B rows, SW128 ----
        {
            const char* sH = (const char*)(whi + (long long)co0 * K + k0);
            const char* sL = (const char*)(wlo + (long long)co0 * K + k0);
            const long long rowb = (long long)K * 2;
#pragma unroll
            for (int j = 0; j < (NTILE * 8 + 255) / 256; ++j) {
                int idx = tid + j * 256;
                if (idx < NTILE * 8) {
                    int r = idx >> 3, c = idx & 7;
                    uint4 hv = *(const uint4*)(sH + r * rowb + c * 16);
                    uint4 lv = *(const uint4*)(sL + r * rowb + c * 16);
                    uint32_t off = SWZ((uint32_t)r * 128u + (uint32_t)c * 16u);
                    *(uint4*)(db + 32768 + off) = hv;
                    *(uint4*)(db + 49152 + off) = lv;
                }
            }
        }
        __syncthreads();

        // ---- MMA: 4 k16 steps, 3 terms ----
#pragma unroll
        for (int s = 0; s < 4; ++s) {
            uint32_t bh[N8T][2];
            if constexpr (N8T == 1) {
                uint32_t ad = bHI + SWZ((uint32_t)((n_base + lr) * 128 + s * 32 + (g & 1) * 16));
                LDSM_X2(bh[0][0], bh[0][1], ad);
            } else {
#pragma unroll
                for (int np = 0; np < N8T / 2; ++np) {
                    int nrow = n_base + np * 16 + (g >> 1) * 8 + lr;
                    uint32_t ad = bHI + SWZ((uint32_t)(nrow * 128 + s * 32 + (g & 1) * 16));
                    LDSM_X4(bh[np*2][0], bh[np*2][1], bh[np*2+1][0], bh[np*2+1][1], ad);
                }
            }
            uint32_t ah[2][4];
#pragma unroll
            for (int mt = 0; mt < 2; ++mt) {
                int krow = s * 16 + (g >> 1) * 8 + lr;
                int colb = (m_base + mt * 16 + (g & 1) * 8) * 2;
                uint32_t ad = aHI + SWZA((uint32_t)(krow * 256 + colb));
                LDSM_X4T(ah[mt][0], ah[mt][1], ah[mt][2], ah[mt][3], ad);
            }
#pragma unroll
            for (int mt = 0; mt < 2; ++mt)
#pragma unroll
                for (int nt = 0; nt < N8T; ++nt)
                    MMA16816(acc[mt][nt], ah[mt], bh[nt]);

            uint32_t al[2][4];
#pragma unroll
            for (int mt = 0; mt < 2; ++mt) {
                int krow = s * 16 + (g >> 1) * 8 + lr;
                int colb = (m_base + mt * 16 + (g & 1) * 8) * 2;
                uint32_t ad = aLO + SWZA((uint32_t)(krow * 256 + colb));
                LDSM_X4T(al[mt][0], al[mt][1], al[mt][2], al[mt][3], ad);
            }
#pragma unroll
            for (int mt = 0; mt < 2; ++mt)
#pragma unroll
                for (int nt = 0; nt < N8T; ++nt)
                    MMA16816(acc[mt][nt], al[mt], bh[nt]);

            uint32_t bl[N8T][2];
            if constexpr (N8T == 1) {
                uint32_t ad = bLO + SWZ((uint32_t)((n_base + lr) * 128 + s * 32 + (g & 1) * 16));
                LDSM_X2(bl[0][0], bl[0][1], ad);
            } else {
#pragma unroll
                for (int np = 0; np < N8T / 2; ++np) {
                    int nrow = n_base + np * 16 + (g >> 1) * 8 + lr;
                    uint32_t ad = bLO + SWZ((uint32_t)(nrow * 128 + s * 32 + (g & 1) * 16));
                    LDSM_X4(bl[np*2][0], bl[np*2][1], bl[np*2+1][0], bl[np*2+1][1], ad);
                }
            }
#pragma unroll
            for (int mt = 0; mt < 2; ++mt)
#pragma unroll
                for (int nt = 0; nt < N8T; ++nt)
                    MMA16816(acc[mt][nt], ah[mt], bl[nt]);
        }
        __syncthreads();
    }

    // ---- epilogue ----
    const long long obase = (long long)bz * ob;
#pragma unroll
    for (int mt = 0; mt < 2; ++mt)
#pragma unroll
        for (int nt = 0; nt < N8T; ++nt)
#pragma unroll
            for (int rg = 0; rg < 4; ++rg) {
                int m  = m_base + mt * 16 + (lane >> 2) + ((rg >= 2) ? 8 : 0);
                int co = co0 + n_base + nt * 8 + (lane & 3) * 2 + (rg & 1);
                if (co < CoutActual) {
                    float v = acc[mt][nt][rg] + bias[co];
                    if (RELU) v = fmaxf(v, 0.f);
                    out[obase + (long long)co * oc + (long long)(p0 + m) * op] = v;
                }
            }
#endif
}

// ---------------- nearest 2x upsample + add ----------------------------------
__global__ void up2add_kernel(float* __restrict__ big, const float* __restrict__ small,
                              int Hs, int Ws)
{
    const int H = Hs * 2, W = Ws * 2;
    const long long total = 8LL * 256 * H * W;
    long long idx = (long long)blockIdx.x * blockDim.x + threadIdx.x;
    if (idx >= total) return;
    int x = (int)(idx % W);
    int y = (int)((idx / W) % H);
    long long bc = idx / ((long long)W * H);
    big[idx] += small[(bc * Hs + (y >> 1)) * Ws + (x >> 1)];
}

// ---------------- anchors ----------------------------------------------------
__global__ void anchors_kernel(float* __restrict__ out)
{
    int i = blockIdx.x * blockDim.x + threadIdx.x;
    if (i >= 16128) return;
    int lvl, rem;
    if (i < 12288)      { lvl = 0; rem = i; }
    else if (i < 15360) { lvl = 1; rem = i - 12288; }
    else                { lvl = 2; rem = i - 15360; }
    const int w        = 64 >> lvl;
    const float stride = 8.0f * (float)(1 << lvl);
    const float bs     = 32.0f * (float)(1 << lvl);
    const int a = rem % 3;
    const int s = rem / 3;
    const int x = s % w;
    const int y = s / w;
    const float sq[3] = {0.70710678118654752f, 1.0f, 1.41421356237309505f};
    const float hw = bs * sq[a] * 0.5f;
    const float hh = bs / sq[a] * 0.5f;
    const float cx = (float)x * stride;
    const float cy = (float)y * stride;
    float* o = out + (long long)i * 4;
    o[0] = cx - hw; o[1] = cy - hh; o[2] = cx + hw; o[3] = cy + hh;
}

// ---------------- host dispatch ----------------------------------------------
static const size_t GEMM_SMEM = 66560;

static void run_gemm(int NT, bool relu, const float* in,
                     const __nv_bfloat16* whi, const __nv_bfloat16* wlo,
                     const float* bias, float* out,
                     int Cin, int coutA, int coutP, int taps, int H, int W,
                     long long ob, long long oc, long long op)
{
    int K = Cin * taps;
    dim3 grid((H * W) / 128, coutP / NT, 8);
    if (NT == 128) {
        if (relu)
            gemm_conv<128, true><<<grid, 256, GEMM_SMEM>>>(in, whi, wlo, bias, out,
                Cin, coutA, K, taps, H, W, ob, oc, op);
        else
            gemm_conv<128, false><<<grid, 256, GEMM_SMEM>>>(in, whi, wlo, bias, out,
                Cin, coutA, K, taps, H, W, ob, oc, op);
    } else {
        gemm_conv<16, false><<<grid, 256, GEMM_SMEM>>>(in, whi, wlo, bias, out,
            Cin, coutA, K, taps, H, W, ob, oc, op);
    }
}

extern "C" void kernel_launch(void* const* d_in, const int* in_sizes, int n_in,
                              void* d_out, int out_size)
{
    const float* feat3 = (const float*)d_in[0];
    const float* feat4 = (const float*)d_in[1];
    const float* feat5 = (const float*)d_in[2];
    const float* lw0 = (const float*)d_in[3];  const float* lb0 = (const float*)d_in[4];
    const float* lw1 = (const float*)d_in[5];  const float* lb1 = (const float*)d_in[6];
    const float* lw2 = (const float*)d_in[7];  const float* lb2 = (const float*)d_in[8];
    const float* fw0 = (const float*)d_in[9];  const float* fb0 = (const float*)d_in[10];
    const float* fw1 = (const float*)d_in[11]; const float* fb1 = (const float*)d_in[12];
    const float* fw2 = (const float*)d_in[13]; const float* fb2 = (const float*)d_in[14];
    const float* cw0 = (const float*)d_in[15]; const float* cb0 = (const float*)d_in[16];
    const float* cw1 = (const float*)d_in[17]; const float* cb1 = (const float*)d_in[18];
    const float* cw2 = (const float*)d_in[19]; const float* cb2 = (const float*)d_in[20];
    const float* rw0 = (const float*)d_in[21]; const float* rb0 = (const float*)d_in[22];
    const float* rw1 = (const float*)d_in[23]; const float* rb1 = (const float*)d_in[24];
    const float* rw2 = (const float*)d_in[25]; const float* rb2 = (const float*)d_in[26];
    float* out = (float*)d_out;

    cudaFuncSetAttribute(gemm_conv<128, false>, cudaFuncAttributeMaxDynamicSharedMemorySize, (int)GEMM_SMEM);
    cudaFuncSetAttribute(gemm_conv<128, true>,  cudaFuncAttributeMaxDynamicSharedMemorySize, (int)GEMM_SMEM);
    cudaFuncSetAttribute(gemm_conv<16,  false>, cudaFuncAttributeMaxDynamicSharedMemorySize, (int)GEMM_SMEM);

    float *l0, *l1, *l2, *f, *t1, *t2;
    __nv_bfloat16 *whi, *wlo;
    cudaGetSymbolAddress((void**)&l0, g_l0);
    cudaGetSymbolAddress((void**)&l1, g_l1);
    cudaGetSymbolAddress((void**)&l2, g_l2);
    cudaGetSymbolAddress((void**)&f,  g_f);
    cudaGetSymbolAddress((void**)&t1, g_t1);
    cudaGetSymbolAddress((void**)&t2, g_t2);
    cudaGetSymbolAddress((void**)&whi, g_whi);
    cudaGetSymbolAddress((void**)&wlo, g_wlo);

    struct WT { const float* src; long long off; int coutA, coutP, cin, taps; };
    const WT wts[12] = {
        { lw0, WOFF_L0,  256, 256, 512,  1 },
        { lw1, WOFF_L1,  256, 256, 1024, 1 },
        { lw2, WOFF_L2,  256, 256, 2048, 1 },
        { fw0, WOFF_FW0, 256, 256, 256,  9 },
        { fw1, WOFF_FW1, 256, 256, 256,  9 },
        { fw2, WOFF_FW2, 256, 256, 256,  9 },
        { cw0, WOFF_CW0, 256, 256, 256,  9 },
        { cw1, WOFF_CW1, 256, 256, 256,  9 },
        { cw2, WOFF_CW2, 240, 256, 256,  9 },
        { rw0, WOFF_RW0, 256, 256, 256,  9 },
        { rw1, WOFF_RW1, 256, 256, 256,  9 },
        { rw2, WOFF_RW2, 12,  16,  256,  9 },
    };
    for (int i = 0; i < 12; ++i) {
        long long n = (long long)wts[i].coutP * wts[i].cin * wts[i].taps;
        wt_kernel<<<(unsigned)((n + 255) / 256), 256>>>(
            wts[i].src, whi + wts[i].off, wlo + wts[i].off,
            wts[i].coutA, n, wts[i].cin, wts[i].taps);
    }

    run_gemm(128, false, feat3, whi + WOFF_L0, wlo + WOFF_L0, lb0, l0,
             512,  256, 256, 1, 64, 64, 256LL * 4096, 4096, 1);
    run_gemm(128, false, feat4, whi + WOFF_L1, wlo + WOFF_L1, lb1, l1,
             1024, 256, 256, 1, 32, 32, 256LL * 1024, 1024, 1);
    run_gemm(128, false, feat5, whi + WOFF_L2, wlo + WOFF_L2, lb2, l2,
             2048, 256, 256, 1, 16, 16, 256LL * 256, 256, 1);

    {
        long long n1 = 8LL * 256 * 32 * 32;
        up2add_kernel<<<(unsigned)((n1 + 255) / 256), 256>>>(l1, l2, 16, 16);
        long long n0 = 8LL * 256 * 64 * 64;
        up2add_kernel<<<(unsigned)((n0 + 255) / 256), 256>>>(l0, l1, 32, 32);
    }

    struct Lvl { const float* lat; long long fwoff; const float* fb; int H, W; long long poff; };
    const Lvl L[3] = {
        { l0, WOFF_FW0, fb0, 64, 64, 0    },
        { l1, WOFF_FW1, fb1, 32, 32, 4096 },
        { l2, WOFF_FW2, fb2, 16, 16, 5120 },
    };

    for (int i = 0; i < 3; ++i) {
        const int H = L[i].H, W = L[i].W;
        const long long hw = (long long)H * W;
        run_gemm(128, false, L[i].lat, whi + L[i].fwoff, wlo + L[i].fwoff, L[i].fb, f,
                 256, 256, 256, 9, H, W, 256 * hw, hw, 1);
        run_gemm(128, true,  f,  whi + WOFF_CW0, wlo + WOFF_CW0, cb0, t1,
                 256, 256, 256, 9, H, W, 256 * hw, hw, 1);
        run_gemm(128, true,  t1, whi + WOFF_CW1, wlo + WOFF_CW1, cb1, t2,
                 256, 256, 256, 9, H, W, 256 * hw, hw, 1);
        run_gemm(128, false, t2, whi + WOFF_CW2, wlo + WOFF_CW2, cb2,
                 out + L[i].poff * 252,
                 256, 240, 256, 9, H, W, 5376LL * 252, 1, 252);
        run_gemm(128, true,  f,  whi + WOFF_RW0, wlo + WOFF_RW0, rb0, t1,
                 256, 256, 256, 9, H, W, 256 * hw, hw, 1);
        run_gemm(128, true,  t1, whi + WOFF_RW1, wlo + WOFF_RW1, rb1, t2,
                 256, 256, 256, 9, H, W, 256 * hw, hw, 1);
        run_gemm(16,  false, t2, whi + WOFF_RW2, wlo + WOFF_RW2, rb2,
                 out + L[i].poff * 252 + 240,
                 256, 12, 16, 9, H, W, 5376LL * 252, 1, 252);
    }

    anchors_kernel<<<(16128 + 255) / 256, 256>>>(out + 10838016LL);
}